// round 9
// baseline (speedup 1.0000x reference)
#include <cuda_runtime.h>
#include <cuda_bf16.h>

// OccupancyGridForestAS: 4.19M points, 8x8x8 block lookup -> 64 trees of 64^3 voxels.
//
// inputs (metadata order):
//   d_in[0]: pts            float32 [N_PTS, 3]
//   d_in[1]: occ_val_grid   float32 [64, 64, 64, 64]
//   d_in[2]: block_lookup   int32   [8, 8, 8]
// output: float32 [N_PTS]
//
// R9: persistent flat grid-stride loop (no barriers in loop), 8 pts per
// thread-iteration: 6x LDG.128 front-batched stream loads + 8 independent
// __ldcg gathers per iter (2x MLP vs R8 on both phases). Grid sized from the
// occupancy API so residency changes never reintroduce wave quantization.
// Cache policy = proven config (__ldcs stream, __ldcg gather, __stcs out).

#define RES   64
#define LDIM  8
#define NTHREADS 256

__global__ void __launch_bounds__(NTHREADS)
occ_forest_kernel(const float4* __restrict__ pts4,
                  const float*  __restrict__ occ,
                  const int*    __restrict__ lut,
                  float4*       __restrict__ out4,
                  int nc)                      // number of 8-point chunks
{
    __shared__ int s_lut[LDIM * LDIM * LDIM];  // 512 ints = 2KB
    {
        int tid = threadIdx.x;
        s_lut[tid]       = lut[tid];
        s_lut[tid + 256] = lut[tid + 256];
    }
    __syncthreads();

    const int stride = gridDim.x * blockDim.x;

    for (int t = blockIdx.x * blockDim.x + threadIdx.x; t < nc; t += stride) {
        // 8 points = 24 floats = 6 float4, issued back-to-back (MLP_p1 = 6)
        float4 v[6];
#pragma unroll
        for (int j = 0; j < 6; j++)
            v[j] = __ldcs(&pts4[6 * t + j]);

        float f[24];
#pragma unroll
        for (int j = 0; j < 6; j++) {
            f[4 * j + 0] = v[j].x;
            f[4 * j + 1] = v[j].y;
            f[4 * j + 2] = v[j].z;
            f[4 * j + 3] = v[j].w;
        }

        int  idx[8];
        bool valid[8];

        // Phase 1: index math for all 8 points (no cross-point dependencies)
#pragma unroll
        for (int i = 0; i < 8; i++) {
            float x = f[3 * i + 0];
            float y = f[3 * i + 1];
            float z = f[3 * i + 2];

            int bx = (int)floorf(x);
            int by = (int)floorf(y);
            int bz = (int)floorf(z);

            bool in_dom = (bx >= 0) & (bx < LDIM) &
                          (by >= 0) & (by < LDIM) &
                          (bz >= 0) & (bz < LDIM);

            int cx = min(max(bx, 0), LDIM - 1);
            int cy = min(max(by, 0), LDIM - 1);
            int cz = min(max(bz, 0), LDIM - 1);

            int bidx = s_lut[cx * (LDIM * LDIM) + cy * LDIM + cz];
            valid[i] = in_dom && (bidx >= 0);

            // Bit-exact reference float sequence:
            //   block_x = 2*(p - bcs) - 1 ; vox = floor((block_x*0.5+0.5)*RES)
            // valid => x-cx in [0,1) => vox in [0,63]; clamps elided
            // (invalid points never issue the load).
            float bxf = 2.0f * (x - (float)cx) - 1.0f;
            float byf = 2.0f * (y - (float)cy) - 1.0f;
            float bzf = 2.0f * (z - (float)cz) - 1.0f;

            int vx = (int)floorf((bxf * 0.5f + 0.5f) * (float)RES);
            int vy = (int)floorf((byf * 0.5f + 0.5f) * (float)RES);
            int vz = (int)floorf((bzf * 0.5f + 0.5f) * (float)RES);

            idx[i] = bidx * (RES * RES * RES) + vx * (RES * RES) + vy * RES + vz;
        }

        // Phase 2: 8 independent predicated gathers (L2-only path)
        float r[8];
#pragma unroll
        for (int i = 0; i < 8; i++)
            r[i] = valid[i] ? __ldcg(&occ[idx[i]]) : 0.0f;

        float4 o0, o1;
        o0.x = r[0]; o0.y = r[1]; o0.z = r[2]; o0.w = r[3];
        o1.x = r[4]; o1.y = r[5]; o1.z = r[6]; o1.w = r[7];
        __stcs(&out4[2 * t + 0], o0);
        __stcs(&out4[2 * t + 1], o1);
    }
}

extern "C" void kernel_launch(void* const* d_in, const int* in_sizes, int n_in,
                              void* d_out, int out_size)
{
    const float4* pts4 = (const float4*)d_in[0];
    const float*  occ  = (const float*)d_in[1];
    const int*    lut  = (const int*)d_in[2];
    float4*       out  = (float4*)d_out;

    int n_pts = in_sizes[0] / 3;       // 4,194,304
    int nc    = n_pts / 8;             // 524,288 8-point chunks

    // Persistent grid sized to exactly one resident wave, whatever the
    // compiler's register count turned occupancy into.
    int blocks_per_sm = 0;
    cudaOccupancyMaxActiveBlocksPerMultiprocessor(
        &blocks_per_sm, occ_forest_kernel, NTHREADS, 0);
    if (blocks_per_sm < 1) blocks_per_sm = 1;

    int dev = 0, nsm = 148;
    cudaGetDevice(&dev);
    cudaDeviceGetAttribute(&nsm, cudaDevAttrMultiProcessorCount, dev);

    int blocks = nsm * blocks_per_sm;
    occ_forest_kernel<<<blocks, NTHREADS>>>(pts4, occ, lut, out, nc);
}